// round 14
// baseline (speedup 1.0000x reference)
#include <cuda_runtime.h>
#include <cstdint>

// GATv2 2-layer forward.
// x[2,1024,128], adj[2,1024,1024] i32, W1[64,128], a1[8], W2[8,64], a2[8]
// out[2,1024,8] f32
//
// Score identity: leaky(s) = 0.6*s + 0.4*|s|; softmax is invariant to the
// per-i constant, so:
//   log2e*e'(i,j,h) = C[j,h] + sum_f (0.4*log2e*a_f)*|g_i,f + g_j,f|
// with C = 0.6*log2e*(a . g) computed in epilogues.
// Max-free softmax (scores O(1); partials sum linearly).
// 3 launches: [gemm1+C1||adj2bits] -> attn1(+ELU+gemm2+C2 fused) -> attn2.
// h1 never touches global memory (row-local gemm2 in attn1's epilogue).

#define LOG2E 1.4426950408889634f
typedef unsigned long long u64;
typedef unsigned int u32;

__device__ __forceinline__ float fexp2(float x) {
    float y;
    asm("ex2.approx.ftz.f32 %0, %1;" : "=f"(y) : "f"(x));
    return y;
}
__device__ __forceinline__ u64 add2(u64 a, u64 b) {
    u64 o; asm("add.rn.f32x2 %0,%1,%2;" : "=l"(o) : "l"(a), "l"(b)); return o;
}
__device__ __forceinline__ u64 mul2(u64 a, u64 b) {
    u64 o; asm("mul.rn.f32x2 %0,%1,%2;" : "=l"(o) : "l"(a), "l"(b)); return o;
}
__device__ __forceinline__ u64 fma2(u64 a, u64 b, u64 c) {
    u64 o; asm("fma.rn.f32x2 %0,%1,%2,%3;" : "=l"(o) : "l"(a), "l"(b), "l"(c)); return o;
}
__device__ __forceinline__ u64 pack2(float lo, float hi) {
    u64 o; asm("mov.b64 %0,{%1,%2};" : "=l"(o) : "f"(lo), "f"(hi)); return o;
}
__device__ __forceinline__ float2 unpack2(u64 a) {
    float2 r; asm("mov.b64 {%0,%1},%2;" : "=f"(r.x), "=f"(r.y) : "l"(a)); return r;
}

// scratch (allocation-free rule: __device__ globals)
__device__ float d_g1[2 * 1024 * 64];
__device__ float d_g2[2 * 1024 * 8];
__device__ float d_c1[2 * 1024 * 8];
__device__ float d_c2[2 * 1024];
__device__ unsigned d_bits[2 * 1024 * 32];

// ---------------------------------------------------------------------------
// Fused pre-pass, single-wave grid of 1024 blocks (16.6KB smem, 8 CTAs/SM):
// Blocks [0,512): gemm1 out[M,64] = X[M,128] @ W[64,128]^T + C1 epilogue,
//   W staged in two 64-column halves (halves smem vs full stage).
// Blocks [512,1024): adjacency->bitmask; each warp packs 512 ints (16 words).
// ---------------------------------------------------------------------------
__global__ __launch_bounds__(256) void fused_pre(
    const int* __restrict__ adj, unsigned* __restrict__ bits,
    const float* __restrict__ X, const float* __restrict__ W,
    const float* __restrict__ A, float* __restrict__ g1,
    float* __restrict__ C) {
    constexpr int D = 128, K = 64, RPB = 4;
    __shared__ float wsh[64 * (K + 1)];   // one D-half of W, padded
    int tid = threadIdx.x;

    if (blockIdx.x >= 512) {  // ---- adj2bits ----
        int abid = blockIdx.x - 512;
        int gw = (abid * 256 + tid) >> 5;   // 4096 warps, 512 ints each
        int lane = tid & 31;
        size_t base = (size_t)gw * 512 + lane;
        int v[16];
#pragma unroll
        for (int k = 0; k < 16; k++) v[k] = adj[base + k * 32];
#pragma unroll
        for (int k = 0; k < 16; k++) {
            unsigned m = __ballot_sync(0xffffffffu, v[k] != 0);
            if (lane == 0) bits[gw * 16 + k] = m;
        }
        return;
    }
    // ---- gemm1 + C1 (two-half W staging) ----
    int bid = blockIdx.x;
    int c = tid % K;
    int r = bid * RPB + tid / K;
    const float4* x4 = (const float4*)(X + (size_t)r * D);
    float a0 = 0.f, a1v = 0.f, a2v = 0.f, a3 = 0.f;
#pragma unroll
    for (int half = 0; half < 2; half++) {
        for (int idx = tid; idx < 64 * K; idx += 256) {
            int cc = idx / 64, dd = idx % 64;
            wsh[dd * (K + 1) + cc] = W[cc * D + half * 64 + dd];
        }
        __syncthreads();
#pragma unroll
        for (int d4 = 0; d4 < 16; d4++) {
            float4 xv = __ldg(x4 + half * 16 + d4);
            a0 = fmaf(xv.x, wsh[(d4 * 4 + 0) * (K + 1) + c], a0);
            a1v = fmaf(xv.y, wsh[(d4 * 4 + 1) * (K + 1) + c], a1v);
            a2v = fmaf(xv.z, wsh[(d4 * 4 + 2) * (K + 1) + c], a2v);
            a3 = fmaf(xv.w, wsh[(d4 * 4 + 3) * (K + 1) + c], a3);
        }
        __syncthreads();
    }
    float acc = (a0 + a1v) + (a2v + a3);
    g1[(size_t)r * K + c] = acc;
    float t = acc * __ldg(A + (c & 7));
    t += __shfl_xor_sync(0xffffffffu, t, 1);
    t += __shfl_xor_sync(0xffffffffu, t, 2);
    t += __shfl_xor_sync(0xffffffffu, t, 4);
    if ((c & 7) == 0) C[(size_t)r * (K / 8) + (c >> 3)] = 0.6f * LOG2E * t;
}

// ---------------------------------------------------------------------------
// attn layer 1: H=8, F=8. CTA = 512 thr = 16 warps = 4 rows x 4 j-splits
// (best-measured shape). TJ=128 tiles, 2 barriers/tile.
// lane = jg*8 + h. g tile stride 12/head (conflict-free LDS.128); C separate,
// stride 8 (conflict-free LDS.32). Staging q-permuted (conflict-free STS.128).
// Epilogue: ELU then fused row-local gemm2 (g2[r] = W2 @ h1[r]) + C2.
// ---------------------------------------------------------------------------
__global__ __launch_bounds__(512, 2) void attn1_kernel(
    const float* __restrict__ G, const unsigned* __restrict__ BITS,
    const float* __restrict__ C, const float* __restrict__ AW,
    const float* __restrict__ W2, const float* __restrict__ A2,
    float* __restrict__ G2, float* __restrict__ C2, int N) {
    constexpr int S = 96;
    constexpr int TJ = 128;

    extern __shared__ float smem[];
    float* gsh = smem;                      // TJ*S
    float* csh = smem + TJ * S;             // TJ*8
    float* psum = csh + TJ * 8;             // 16*8*9
    float* w2sh = psum + 16 * 8 * 9;        // 8*64

    int tid = threadIdx.x;
    int w = tid >> 5, lane = tid & 31;
    int r = w & 3, sp = w >> 2;
    int h = lane & 7, jg = lane >> 3;
    int base = sp * 4 + jg;            // [0,16)

    int iflat = blockIdx.x * 4 + r;
    int b = iflat >> 10;

    if (tid < 512) w2sh[tid] = W2[tid];

    const float* gp = G + (size_t)iflat * 64 + h * 8;
    float4 gi0 = *(const float4*)gp;
    float4 gi1 = *(const float4*)(gp + 4);
    u64 gp01 = pack2(gi0.x, gi0.y), gp23 = pack2(gi0.z, gi0.w);
    u64 gp45 = pack2(gi1.x, gi1.y), gp67 = pack2(gi1.z, gi1.w);

    u64 aw[4];
#pragma unroll
    for (int k = 0; k < 4; k++)
        aw[k] = pack2(0.4f * LOG2E * __ldg(AW + 2 * k),
                      0.4f * LOG2E * __ldg(AW + 2 * k + 1));
    const u64 amask = 0x7fffffff7fffffffULL;

    float l = 0.f;
    u64 a01 = 0, a23 = 0, a45 = 0, a67 = 0;

    const float4* gbase = (const float4*)(G + (size_t)b * N * 64);
    const float* cbase = C + (size_t)b * N * 8;
    const unsigned* bitsrow = BITS + (size_t)iflat * 32;
    const float* gl = gsh + base * S + h * 12;
    const float* cl = csh + base * 8 + h;

    for (int jt = 0; jt < N; jt += TJ) {
        __syncthreads();
        const float4* src = gbase + (size_t)jt * 16;
        for (int idx = tid; idx < TJ * 16; idx += 512) {
            int j = idx >> 4, qidx = idx & 15;
            int q = ((qidx & 7) << 1) | (qidx >> 3);
            *(float4*)&gsh[j * S + (q >> 1) * 12 + (q & 1) * 4] = src[(j << 4) | q];
        }
        const float* csrc = cbase + (size_t)jt * 8;
        for (int idx = tid; idx < TJ * 8; idx += 512) csh[idx] = csrc[idx];
        __syncthreads();

        uint4 bw = *(const uint4*)(bitsrow + (jt >> 5));
#pragma unroll
        for (int k = 0; k < 8; k++) {
            const float* gr = gl + k * (16 * S);
            ulonglong2 v0 = *(const ulonglong2*)gr;
            ulonglong2 v1 = *(const ulonglong2*)(gr + 4);
            float cj = cl[k * 128];
            unsigned wv = (k < 2) ? bw.x : (k < 4) ? bw.y : (k < 6) ? bw.z : bw.w;
            unsigned m = (wv >> (base + ((k & 1) << 4))) & 1u;

            u64 s01 = add2(gp01, v0.x), s23 = add2(gp23, v0.y);
            u64 s45 = add2(gp45, v1.x), s67 = add2(gp67, v1.y);
            u64 d = mul2(aw[0], s01 & amask);
            d = fma2(aw[1], s23 & amask, d);
            d = fma2(aw[2], s45 & amask, d);
            d = fma2(aw[3], s67 & amask, d);
            float2 ev = unpack2(d);
            float e = (ev.x + ev.y) + cj;
            float wgt = m ? fexp2(e) : 0.f;
            l += wgt;
            u64 wp = pack2(wgt, wgt);
            a01 = fma2(wp, v0.x, a01);
            a23 = fma2(wp, v0.y, a23);
            a45 = fma2(wp, v1.x, a45);
            a67 = fma2(wp, v1.y, a67);
        }
    }

    float2 f01 = unpack2(a01), f23 = unpack2(a23), f45 = unpack2(a45), f67 = unpack2(a67);
    float acc[8] = {f01.x, f01.y, f23.x, f23.y, f45.x, f45.y, f67.x, f67.y};
#pragma unroll
    for (int off = 8; off < 32; off <<= 1) {
        l += __shfl_xor_sync(0xffffffffu, l, off);
#pragma unroll
        for (int f = 0; f < 8; f++) acc[f] += __shfl_xor_sync(0xffffffffu, acc[f], off);
    }

    if (jg == 0) {
        float* p = psum + (w * 8 + h) * 9;
        p[0] = l;
#pragma unroll
        for (int f = 0; f < 8; f++) p[1 + f] = acc[f];
    }
    __syncthreads();
    if (sp == 0 && jg == 0) {   // warps 0..3 (w == r), lanes 0..7 (lane == h)
        float L = 0.f, A[8] = {0, 0, 0, 0, 0, 0, 0, 0};
#pragma unroll
        for (int ss = 0; ss < 4; ss++) {
            const float* p = psum + ((ss * 4 + r) * 8 + h) * 9;
            L += p[0];
#pragma unroll
            for (int f = 0; f < 8; f++) A[f] += p[1 + f];
        }
        float inv = 1.f / L;
        float o[8];
#pragma unroll
        for (int f = 0; f < 8; f++) {
            o[f] = A[f] * inv;
            o[f] = o[f] > 0.f ? o[f] : fexp2(o[f] * LOG2E) - 1.f;  // ELU
        }
        // fused gemm2: pk[k] = sum_f W2[k, h*8+f] * o[f]; reduce over 8 h-lanes
        float pk[8];
#pragma unroll
        for (int k = 0; k < 8; k++) {
            const float* wrow = w2sh + k * 64 + h * 8;
            float s = wrow[0] * o[0];
            s = fmaf(wrow[1], o[1], s);
            s = fmaf(wrow[2], o[2], s);
            s = fmaf(wrow[3], o[3], s);
            s = fmaf(wrow[4], o[4], s);
            s = fmaf(wrow[5], o[5], s);
            s = fmaf(wrow[6], o[6], s);
            s = fmaf(wrow[7], o[7], s);
            pk[k] = s;
        }
#pragma unroll
        for (int off = 1; off < 8; off <<= 1) {
#pragma unroll
            for (int k = 0; k < 8; k++)
                pk[k] += __shfl_xor_sync(0x000000ffu, pk[k], off);
        }
        if (h == 0) {
            float* op = G2 + (size_t)iflat * 8;
            *(float4*)op = make_float4(pk[0], pk[1], pk[2], pk[3]);
            *(float4*)(op + 4) = make_float4(pk[4], pk[5], pk[6], pk[7]);
            float cacc = 0.f;
#pragma unroll
            for (int k = 0; k < 8; k++) cacc = fmaf(pk[k], __ldg(A2 + k), cacc);
            C2[iflat] = 0.6f * LOG2E * cacc;
        }
    }
}

// ---------------------------------------------------------------------------
// attn layer 2: H=1, F=8. CTA = 512 thr = 16 warps = 8 rows x 2 j-splits,
// grid 256 (same CTA count/staging total as the 10.2us version, but 2x the
// staging rate and warps in flight). Whole g2 batch staged once; C separate
// stride-1. Lane L owns j = L + 32k; warp (sp,r): kk in [sp*4, sp*4+4).
// ---------------------------------------------------------------------------
__global__ __launch_bounds__(512) void attn2_kernel(
    const float* __restrict__ G, const unsigned* __restrict__ BITS,
    const float* __restrict__ C, const float* __restrict__ AW,
    float* __restrict__ OUT, int N) {
    extern __shared__ float smem[];
    float* gsh = smem;            // N*12
    float* csh = smem + N * 12;   // N
    float* psum = csh + N;        // 16*9

    int tid = threadIdx.x;
    int w = tid >> 5, lane = tid & 31;
    int r = w & 7, sp = w >> 3;
    int iflat = blockIdx.x * 8 + r;
    int b = iflat >> 10;

    const float4* gb = (const float4*)(G + (size_t)b * N * 8);
    const float* cb = C + (size_t)b * N;
    {
        // phase: 128-thread groups write same-q, consecutive-j (conflict-free)
        int part = tid >> 8, t2 = tid & 255;
        int jb = t2 & 127, q = t2 >> 7;
#pragma unroll
        for (int it = 0; it < 4; it++) {
            int j = jb + part * 128 + it * 256;
            *(float4*)&gsh[j * 12 + q * 4] = gb[j * 2 + q];
        }
    }
    for (int idx = tid; idx < N; idx += 512) csh[idx] = cb[idx];
    __syncthreads();

    const float* gp = G + (size_t)iflat * 8;
    float4 gi0 = *(const float4*)gp;
    float4 gi1 = *(const float4*)(gp + 4);
    u64 gp01 = pack2(gi0.x, gi0.y), gp23 = pack2(gi0.z, gi0.w);
    u64 gp45 = pack2(gi1.x, gi1.y), gp67 = pack2(gi1.z, gi1.w);

    u64 aw[4];
#pragma unroll
    for (int k = 0; k < 4; k++)
        aw[k] = pack2(0.4f * LOG2E * __ldg(AW + 2 * k),
                      0.4f * LOG2E * __ldg(AW + 2 * k + 1));
    const u64 amask = 0x7fffffff7fffffffULL;

    const uint4* b4 = (const uint4*)(BITS + (size_t)iflat * 32);
    const float* gl = gsh + lane * 12;
    const float* cl = csh + lane;

    float l = 0.f;
    u64 a01 = 0, a23 = 0, a45 = 0, a67 = 0;

#pragma unroll
    for (int kx = 0; kx < 4; kx++) {
        int kk = sp * 4 + kx;
        uint4 bw = b4[kk];
#pragma unroll
        for (int k2 = 0; k2 < 4; k2++) {
            const float* gr = gl + (kk * 4 + k2) * (32 * 12);
            ulonglong2 v0 = *(const ulonglong2*)gr;
            ulonglong2 v1 = *(const ulonglong2*)(gr + 4);
            float cj = cl[(kk * 4 + k2) * 32];
            unsigned wv = (k2 == 0) ? bw.x : (k2 == 1) ? bw.y : (k2 == 2) ? bw.z : bw.w;
            unsigned m = (wv >> lane) & 1u;

            u64 s01 = add2(gp01, v0.x), s23 = add2(gp23, v0.y);
            u64 s45 = add2(gp45, v1.x), s67 = add2(gp67, v1.y);
            u64 d = mul2(aw[0], s01 & amask);
            d = fma2(aw[1], s23 & amask, d);
            d = fma2(aw[2], s45 & amask, d);
            d = fma2(aw[3], s67 & amask, d);
            float2 ev = unpack2(d);
            float e = (ev.x + ev.y) + cj;
            float wgt = m ? fexp2(e) : 0.f;
            l += wgt;
            u64 wp = pack2(wgt, wgt);
            a01 = fma2(wp, v0.x, a01);
            a23 = fma2(wp, v0.y, a23);
            a45 = fma2(wp, v1.x, a45);
            a67 = fma2(wp, v1.y, a67);
        }
    }

    float2 f01 = unpack2(a01), f23 = unpack2(a23), f45 = unpack2(a45), f67 = unpack2(a67);
    float acc[8] = {f01.x, f01.y, f23.x, f23.y, f45.x, f45.y, f67.x, f67.y};
#pragma unroll
    for (int off = 1; off < 32; off <<= 1) {
        l += __shfl_xor_sync(0xffffffffu, l, off);
#pragma unroll
        for (int f = 0; f < 8; f++) acc[f] += __shfl_xor_sync(0xffffffffu, acc[f], off);
    }

    if (lane == 0) {
        float* p = psum + w * 9;
        p[0] = l;
#pragma unroll
        for (int f = 0; f < 8; f++) p[1 + f] = acc[f];
    }
    __syncthreads();
    if (sp == 0 && lane == 0) {   // warps 0..7, one per row
        const float* p0 = psum + w * 9;
        const float* p1 = psum + (w + 8) * 9;
        float inv = 1.f / (p0[0] + p1[0]);
        float* op = OUT + (size_t)iflat * 8;
#pragma unroll
        for (int f = 0; f < 8; f++) op[f] = (p0[1 + f] + p1[1 + f]) * inv;
    }
}

// ---------------------------------------------------------------------------

extern "C" void kernel_launch(void* const* d_in, const int* in_sizes, int n_in,
                              void* d_out, int out_size) {
    const float* x = (const float*)d_in[0];
    const int* adj = (const int*)d_in[1];
    const float* W1 = (const float*)d_in[2];
    const float* a1 = (const float*)d_in[3];
    const float* W2 = (const float*)d_in[4];
    const float* a2 = (const float*)d_in[5];
    float* out = (float*)d_out;

    const int B = 2, N = 1024, M = B * N;

    float *g1, *g2, *c1, *c2;
    unsigned* bits;
    cudaGetSymbolAddress((void**)&g1, d_g1);
    cudaGetSymbolAddress((void**)&g2, d_g2);
    cudaGetSymbolAddress((void**)&c1, d_c1);
    cudaGetSymbolAddress((void**)&c2, d_c2);
    cudaGetSymbolAddress((void**)&bits, d_bits);

    const int SMEM1 = (128 * 96 + 128 * 8 + 16 * 8 * 9 + 512) * 4;  // 59904
    const int SMEM2 = (N * 12 + N + 16 * 9) * 4;                     // 53824
    cudaFuncSetAttribute((const void*)attn1_kernel,
                         cudaFuncAttributeMaxDynamicSharedMemorySize, SMEM1);
    cudaFuncSetAttribute((const void*)attn2_kernel,
                         cudaFuncAttributeMaxDynamicSharedMemorySize, SMEM2);

    // K1: gemm1+C1 (blocks 0..511) || adj2bits (blocks 512..1023), one wave
    fused_pre<<<1024, 256>>>(adj, bits, x, W1, a1, g1, c1);
    // K2: attn1 (+ELU +gemm2 +C2 fused)
    attn1_kernel<<<M / 4, 512, SMEM1>>>(g1, bits, c1, a1, W2, a2, g2, c2, N);
    // K3: attn2 (8 rows x 2 splits, 512 thr, grid 256)
    attn2_kernel<<<M / 8, 512, SMEM2>>>(g2, bits, c2, a2, out, N);
}

// round 15
// speedup vs baseline: 1.0774x; 1.0774x over previous
#include <cuda_runtime.h>
#include <cstdint>

// GATv2 2-layer forward.
// x[2,1024,128], adj[2,1024,1024] i32, W1[64,128], a1[8], W2[8,64], a2[8]
// out[2,1024,8] f32
//
// 3 launches: gemm1 -> attn1(+ELU+gemm2+C2+bits fused) -> attn2.
// attn1 stages adjacency ints per tile (R3-measured fastest form, inline
// leaky score: leaky(s) = 0.6*(s + (2/3)|s|), 0.6*log2e folded into a1) and
// ballot-packs the staged ints into the bitmask attn2 consumes (free).
// attn2 uses the softmax-invariant C2 trick: e' = C2[j] + 0.4*log2e*sum|s|.
// Max-free softmax throughout (scores O(1); partials sum linearly).
// h1 never touches global memory (row-local gemm2 in attn1's epilogue).

#define LOG2E 1.4426950408889634f
typedef unsigned long long u64;
typedef unsigned int u32;

__device__ __forceinline__ float fexp2(float x) {
    float y;
    asm("ex2.approx.ftz.f32 %0, %1;" : "=f"(y) : "f"(x));
    return y;
}
__device__ __forceinline__ u64 add2(u64 a, u64 b) {
    u64 o; asm("add.rn.f32x2 %0,%1,%2;" : "=l"(o) : "l"(a), "l"(b)); return o;
}
__device__ __forceinline__ u64 mul2(u64 a, u64 b) {
    u64 o; asm("mul.rn.f32x2 %0,%1,%2;" : "=l"(o) : "l"(a), "l"(b)); return o;
}
__device__ __forceinline__ u64 fma2(u64 a, u64 b, u64 c) {
    u64 o; asm("fma.rn.f32x2 %0,%1,%2,%3;" : "=l"(o) : "l"(a), "l"(b), "l"(c)); return o;
}
__device__ __forceinline__ u64 pack2(float lo, float hi) {
    u64 o; asm("mov.b64 %0,{%1,%2};" : "=l"(o) : "f"(lo), "f"(hi)); return o;
}
__device__ __forceinline__ float2 unpack2(u64 a) {
    float2 r; asm("mov.b64 {%0,%1},%2;" : "=f"(r.x), "=f"(r.y) : "l"(a)); return r;
}

// scratch (allocation-free rule: __device__ globals)
__device__ float d_g1[2 * 1024 * 64];
__device__ float d_g2[2 * 1024 * 8];
__device__ float d_c2[2 * 1024];
__device__ unsigned d_bits[2 * 1024 * 32];

// ---------------------------------------------------------------------------
// gemm1: out[M,64] = X[M,128] @ W1[64,128]^T. Two-half W staging (16.6KB).
// ---------------------------------------------------------------------------
__global__ __launch_bounds__(256) void gemm1_kernel(
    const float* __restrict__ X, const float* __restrict__ W,
    float* __restrict__ out) {
    constexpr int D = 128, K = 64, RPB = 4;
    __shared__ float wsh[64 * (K + 1)];
    int tid = threadIdx.x;
    int c = tid % K;
    int r = blockIdx.x * RPB + tid / K;
    const float4* x4 = (const float4*)(X + (size_t)r * D);
    float a0 = 0.f, a1v = 0.f, a2v = 0.f, a3 = 0.f;
#pragma unroll
    for (int half = 0; half < 2; half++) {
        for (int idx = tid; idx < 64 * K; idx += 256) {
            int cc = idx / 64, dd = idx % 64;
            wsh[dd * (K + 1) + cc] = W[cc * D + half * 64 + dd];
        }
        __syncthreads();
#pragma unroll
        for (int d4 = 0; d4 < 16; d4++) {
            float4 xv = __ldg(x4 + half * 16 + d4);
            a0 = fmaf(xv.x, wsh[(d4 * 4 + 0) * (K + 1) + c], a0);
            a1v = fmaf(xv.y, wsh[(d4 * 4 + 1) * (K + 1) + c], a1v);
            a2v = fmaf(xv.z, wsh[(d4 * 4 + 2) * (K + 1) + c], a2v);
            a3 = fmaf(xv.w, wsh[(d4 * 4 + 3) * (K + 1) + c], a3);
        }
        __syncthreads();
    }
    out[(size_t)r * K + c] = (a0 + a1v) + (a2v + a3);
}

// ---------------------------------------------------------------------------
// attn layer 1: H=8, F=8. CTA = 512 thr = 16 warps = 4 rows x 4 j-splits.
// TJ=128 tiles; adjacency INTS staged to smem each tile (R3-measured form),
// ballot-packed to the global bitmask as a byproduct (for attn2).
// Inline score: e = sum_f (0.6*log2e*a_f)*(s + (2/3)|s|), s = g_i + g_j.
// lane = jg*8 + h. g tile stride 12/head (conflict-free LDS.128); staging
// q-permuted (conflict-free STS.128); adj LDS.32 is 4-addr broadcast.
// Epilogue: ELU then fused row-local gemm2 (g2[r] = W2 @ h1[r]) + C2.
// ---------------------------------------------------------------------------
__global__ __launch_bounds__(512, 2) void attn1_kernel(
    const float* __restrict__ G, const int* __restrict__ ADJ,
    const float* __restrict__ AW,
    const float* __restrict__ W2, const float* __restrict__ A2,
    float* __restrict__ G2, float* __restrict__ C2,
    unsigned* __restrict__ BITSOUT, int N) {
    constexpr int S = 96;
    constexpr int TJ = 128;

    extern __shared__ float smem[];
    float* gsh = smem;                      // TJ*S        = 12288
    float* psum = gsh + TJ * S;             // 16*8*9      = 1152
    float* w2sh = psum + 16 * 8 * 9;        // 8*64        = 512
    int* ash = (int*)(w2sh + 512);          // 4*TJ        = 512 ints

    int tid = threadIdx.x;
    int w = tid >> 5, lane = tid & 31;
    int r = w & 3, sp = w >> 2;
    int h = lane & 7, jg = lane >> 3;
    int base = sp * 4 + jg;            // [0,16)

    int iflat = blockIdx.x * 4 + r;
    int b = iflat >> 10;
    int i0 = (blockIdx.x * 4) & 1023;

    if (tid < 512) w2sh[tid] = W2[tid];

    const float* gp = G + (size_t)iflat * 64 + h * 8;
    float4 gi0 = *(const float4*)gp;
    float4 gi1 = *(const float4*)(gp + 4);
    u64 gp01 = pack2(gi0.x, gi0.y), gp23 = pack2(gi0.z, gi0.w);
    u64 gp45 = pack2(gi1.x, gi1.y), gp67 = pack2(gi1.z, gi1.w);

    u64 aw[4];
#pragma unroll
    for (int k = 0; k < 4; k++)
        aw[k] = pack2(0.6f * LOG2E * __ldg(AW + 2 * k),
                      0.6f * LOG2E * __ldg(AW + 2 * k + 1));
    const u64 c23 = pack2(2.f / 3.f, 2.f / 3.f);
    const u64 amask = 0x7fffffff7fffffffULL;

    float l = 0.f;
    u64 a01 = 0, a23 = 0, a45 = 0, a67 = 0;

    const float4* gbase = (const float4*)(G + (size_t)b * N * 64);
    const int* abase = ADJ + (size_t)b * N * N + (size_t)i0 * N;
    const float* gl = gsh + base * S + h * 12;

    // this thread's adjacency staging slot: row srr, column sj of the tile
    int srr = tid >> 7, sj = tid & 127;
    unsigned* bitsrow = BITSOUT + (size_t)(blockIdx.x * 4 + srr) * 32;
    int sword = (tid >> 5) & 3;        // word within tile for this warp

    for (int jt = 0; jt < N; jt += TJ) {
        __syncthreads();
        const float4* src = gbase + (size_t)jt * 16;
        for (int idx = tid; idx < TJ * 16; idx += 512) {
            int j = idx >> 4, qidx = idx & 15;
            int q = ((qidx & 7) << 1) | (qidx >> 3);
            *(float4*)&gsh[j * S + (q >> 1) * 12 + (q & 1) * 4] = src[(j << 4) | q];
        }
        {   // adjacency ints: one per thread; ballot-pack bits as byproduct
            int v = __ldg(abase + (size_t)srr * N + jt + sj);
            ash[tid] = v;
            unsigned mword = __ballot_sync(0xffffffffu, v != 0);
            if (lane == 0) bitsrow[(jt >> 5) + sword] = mword;
        }
        __syncthreads();

#pragma unroll
        for (int k = 0; k < 8; k++) {
            const float* gr = gl + k * (16 * S);
            ulonglong2 v0 = *(const ulonglong2*)gr;
            ulonglong2 v1 = *(const ulonglong2*)(gr + 4);
            int m = ash[r * TJ + base + 16 * k];

            u64 s01 = add2(gp01, v0.x), s23 = add2(gp23, v0.y);
            u64 s45 = add2(gp45, v1.x), s67 = add2(gp67, v1.y);
            u64 d = mul2(aw[0], fma2(s01 & amask, c23, s01));
            d = fma2(aw[1], fma2(s23 & amask, c23, s23), d);
            d = fma2(aw[2], fma2(s45 & amask, c23, s45), d);
            d = fma2(aw[3], fma2(s67 & amask, c23, s67), d);
            float2 ev = unpack2(d);
            float wgt = m ? fexp2(ev.x + ev.y) : 0.f;
            l += wgt;
            u64 wp = pack2(wgt, wgt);
            a01 = fma2(wp, v0.x, a01);
            a23 = fma2(wp, v0.y, a23);
            a45 = fma2(wp, v1.x, a45);
            a67 = fma2(wp, v1.y, a67);
        }
    }

    // intra-warp reduce across jg strips (plain sums — max-free softmax)
    float2 f01 = unpack2(a01), f23 = unpack2(a23), f45 = unpack2(a45), f67 = unpack2(a67);
    float acc[8] = {f01.x, f01.y, f23.x, f23.y, f45.x, f45.y, f67.x, f67.y};
#pragma unroll
    for (int off = 8; off < 32; off <<= 1) {
        l += __shfl_xor_sync(0xffffffffu, l, off);
#pragma unroll
        for (int f = 0; f < 8; f++) acc[f] += __shfl_xor_sync(0xffffffffu, acc[f], off);
    }

    if (jg == 0) {
        float* p = psum + (w * 8 + h) * 9;
        p[0] = l;
#pragma unroll
        for (int f = 0; f < 8; f++) p[1 + f] = acc[f];
    }
    __syncthreads();
    if (sp == 0 && jg == 0) {   // warps 0..3 (w == r), lanes 0..7 (lane == h)
        float L = 0.f, A[8] = {0, 0, 0, 0, 0, 0, 0, 0};
#pragma unroll
        for (int ss = 0; ss < 4; ss++) {
            const float* p = psum + ((ss * 4 + r) * 8 + h) * 9;
            L += p[0];
#pragma unroll
            for (int f = 0; f < 8; f++) A[f] += p[1 + f];
        }
        float inv = 1.f / L;
        float o[8];
#pragma unroll
        for (int f = 0; f < 8; f++) {
            o[f] = A[f] * inv;
            o[f] = o[f] > 0.f ? o[f] : fexp2(o[f] * LOG2E) - 1.f;  // ELU
        }
        // fused gemm2: pk[k] = sum_f W2[k, h*8+f] * o[f]; reduce over 8 h-lanes
        float pk[8];
#pragma unroll
        for (int k = 0; k < 8; k++) {
            const float* wrow = w2sh + k * 64 + h * 8;
            float s = wrow[0] * o[0];
            s = fmaf(wrow[1], o[1], s);
            s = fmaf(wrow[2], o[2], s);
            s = fmaf(wrow[3], o[3], s);
            s = fmaf(wrow[4], o[4], s);
            s = fmaf(wrow[5], o[5], s);
            s = fmaf(wrow[6], o[6], s);
            s = fmaf(wrow[7], o[7], s);
            pk[k] = s;
        }
#pragma unroll
        for (int off = 1; off < 8; off <<= 1) {
#pragma unroll
            for (int k = 0; k < 8; k++)
                pk[k] += __shfl_xor_sync(0x000000ffu, pk[k], off);
        }
        if (h == 0) {
            float* op = G2 + (size_t)iflat * 8;
            *(float4*)op = make_float4(pk[0], pk[1], pk[2], pk[3]);
            *(float4*)(op + 4) = make_float4(pk[4], pk[5], pk[6], pk[7]);
            float cacc = 0.f;
#pragma unroll
            for (int k = 0; k < 8; k++) cacc = fmaf(pk[k], __ldg(A2 + k), cacc);
            C2[iflat] = 0.6f * LOG2E * cacc;
        }
    }
}

// ---------------------------------------------------------------------------
// attn layer 2: H=1, F=8 (best-measured R10 form). CTA = 256 thr = 8 warps =
// 8 rows, grid 256. Whole g2 batch staged once; C2 separate stride-1.
// Lane L owns j = L + 32k; 32 fully-unrolled iterations; full-warp reduce.
// Score uses the softmax-invariant C2 trick: e = C2[j] + 0.4*log2e*sum a|s|.
// ---------------------------------------------------------------------------
__global__ __launch_bounds__(256) void attn2_kernel(
    const float* __restrict__ G, const unsigned* __restrict__ BITS,
    const float* __restrict__ C, const float* __restrict__ AW,
    float* __restrict__ OUT, int N) {
    extern __shared__ float smem[];
    float* gsh = smem;            // N*12
    float* csh = smem + N * 12;   // N

    int tid = threadIdx.x;
    int w = tid >> 5, lane = tid & 31;
    int iflat = blockIdx.x * 8 + w;
    int b = iflat >> 10;

    const float4* gb = (const float4*)(G + (size_t)b * N * 8);
    const float* cb = C + (size_t)b * N;
    {
        int jb = tid & 127, q = tid >> 7;  // phase: same q, consecutive j
#pragma unroll
        for (int it = 0; it < 8; it++) {
            int j = jb + it * 128;
            *(float4*)&gsh[j * 12 + q * 4] = gb[j * 2 + q];
        }
    }
    for (int idx = tid; idx < N; idx += 256) csh[idx] = cb[idx];
    __syncthreads();

    const float* gp = G + (size_t)iflat * 8;
    float4 gi0 = *(const float4*)gp;
    float4 gi1 = *(const float4*)(gp + 4);
    u64 gp01 = pack2(gi0.x, gi0.y), gp23 = pack2(gi0.z, gi0.w);
    u64 gp45 = pack2(gi1.x, gi1.y), gp67 = pack2(gi1.z, gi1.w);

    u64 aw[4];
#pragma unroll
    for (int k = 0; k < 4; k++)
        aw[k] = pack2(0.4f * LOG2E * __ldg(AW + 2 * k),
                      0.4f * LOG2E * __ldg(AW + 2 * k + 1));
    const u64 amask = 0x7fffffff7fffffffULL;

    const uint4* b4 = (const uint4*)(BITS + (size_t)iflat * 32);
    const float* gl = gsh + lane * 12;
    const float* cl = csh + lane;

    float l = 0.f;
    u64 a01 = 0, a23 = 0, a45 = 0, a67 = 0;

#pragma unroll
    for (int kk = 0; kk < 8; kk++) {
        uint4 bw = b4[kk];
#pragma unroll
        for (int k2 = 0; k2 < 4; k2++) {
            const float* gr = gl + (kk * 4 + k2) * (32 * 12);
            ulonglong2 v0 = *(const ulonglong2*)gr;
            ulonglong2 v1 = *(const ulonglong2*)(gr + 4);
            float cj = cl[(kk * 4 + k2) * 32];
            unsigned wv = (k2 == 0) ? bw.x : (k2 == 1) ? bw.y : (k2 == 2) ? bw.z : bw.w;
            unsigned m = (wv >> lane) & 1u;

            u64 s01 = add2(gp01, v0.x), s23 = add2(gp23, v0.y);
            u64 s45 = add2(gp45, v1.x), s67 = add2(gp67, v1.y);
            u64 d = mul2(aw[0], s01 & amask);
            d = fma2(aw[1], s23 & amask, d);
            d = fma2(aw[2], s45 & amask, d);
            d = fma2(aw[3], s67 & amask, d);
            float2 ev = unpack2(d);
            float e = (ev.x + ev.y) + cj;
            float wgt = m ? fexp2(e) : 0.f;
            l += wgt;
            u64 wp = pack2(wgt, wgt);
            a01 = fma2(wp, v0.x, a01);
            a23 = fma2(wp, v0.y, a23);
            a45 = fma2(wp, v1.x, a45);
            a67 = fma2(wp, v1.y, a67);
        }
    }

    float2 f01 = unpack2(a01), f23 = unpack2(a23), f45 = unpack2(a45), f67 = unpack2(a67);
    float acc[8] = {f01.x, f01.y, f23.x, f23.y, f45.x, f45.y, f67.x, f67.y};
#pragma unroll
    for (int off = 1; off < 32; off <<= 1) {
        l += __shfl_xor_sync(0xffffffffu, l, off);
#pragma unroll
        for (int f = 0; f < 8; f++) acc[f] += __shfl_xor_sync(0xffffffffu, acc[f], off);
    }

    if (lane == 0) {
        float inv = 1.f / l;
        float* op = OUT + (size_t)iflat * 8;
        *(float4*)op = make_float4(acc[0] * inv, acc[1] * inv, acc[2] * inv, acc[3] * inv);
        *(float4*)(op + 4) = make_float4(acc[4] * inv, acc[5] * inv, acc[6] * inv, acc[7] * inv);
    }
}

// ---------------------------------------------------------------------------

extern "C" void kernel_launch(void* const* d_in, const int* in_sizes, int n_in,
                              void* d_out, int out_size) {
    const float* x = (const float*)d_in[0];
    const int* adj = (const int*)d_in[1];
    const float* W1 = (const float*)d_in[2];
    const float* a1 = (const float*)d_in[3];
    const float* W2 = (const float*)d_in[4];
    const float* a2 = (const float*)d_in[5];
    float* out = (float*)d_out;

    const int B = 2, N = 1024, M = B * N;

    float *g1, *g2, *c2;
    unsigned* bits;
    cudaGetSymbolAddress((void**)&g1, d_g1);
    cudaGetSymbolAddress((void**)&g2, d_g2);
    cudaGetSymbolAddress((void**)&c2, d_c2);
    cudaGetSymbolAddress((void**)&bits, d_bits);

    const int SMEM1 = (128 * 96 + 16 * 8 * 9 + 512 + 512) * 4;  // 57856
    const int SMEM2 = (N * 12 + N) * 4;                          // 53248
    cudaFuncSetAttribute((const void*)attn1_kernel,
                         cudaFuncAttributeMaxDynamicSharedMemorySize, SMEM1);
    cudaFuncSetAttribute((const void*)attn2_kernel,
                         cudaFuncAttributeMaxDynamicSharedMemorySize, SMEM2);

    // K1: gemm1
    gemm1_kernel<<<512, 256>>>(x, W1, g1);
    // K2: attn1 (+ELU +gemm2 +C2 +bitmask production fused)
    attn1_kernel<<<M / 4, 512, SMEM1>>>(g1, adj, a1, W2, a2, g2, c2, bits, N);
    // K3: attn2
    attn2_kernel<<<M / 8, 256, SMEM2>>>(g2, bits, c2, a2, out, N);
}

// round 16
// speedup vs baseline: 1.0932x; 1.0146x over previous
#include <cuda_runtime.h>
#include <cstdint>

// GATv2 2-layer forward.
// x[2,1024,128], adj[2,1024,1024] i32, W1[64,128], a1[8], W2[8,64], a2[8]
// out[2,1024,8] f32
//
// 3 launches: gemm1 -> attn1(+ELU+gemm2+C2+bits fused) -> attn2.
// attn1 stages adjacency ints per tile (R3-measured fastest form, inline
// leaky score: leaky(s) = 0.6*(s + (2/3)|s|), 0.6*log2e folded into a1) and
// ballot-packs the staged ints into the bitmask attn2 consumes (free).
// attn2 uses the softmax-invariant C2 trick: e' = C2[j] + 0.4*log2e*sum|s|.
// Max-free softmax throughout (scores O(1); partials sum linearly).
// h1 never touches global memory (row-local gemm2 in attn1's epilogue).

#define LOG2E 1.4426950408889634f
typedef unsigned long long u64;
typedef unsigned int u32;

__device__ __forceinline__ float fexp2(float x) {
    float y;
    asm("ex2.approx.ftz.f32 %0, %1;" : "=f"(y) : "f"(x));
    return y;
}
__device__ __forceinline__ u64 add2(u64 a, u64 b) {
    u64 o; asm("add.rn.f32x2 %0,%1,%2;" : "=l"(o) : "l"(a), "l"(b)); return o;
}
__device__ __forceinline__ u64 mul2(u64 a, u64 b) {
    u64 o; asm("mul.rn.f32x2 %0,%1,%2;" : "=l"(o) : "l"(a), "l"(b)); return o;
}
__device__ __forceinline__ u64 fma2(u64 a, u64 b, u64 c) {
    u64 o; asm("fma.rn.f32x2 %0,%1,%2,%3;" : "=l"(o) : "l"(a), "l"(b), "l"(c)); return o;
}
__device__ __forceinline__ u64 pack2(float lo, float hi) {
    u64 o; asm("mov.b64 %0,{%1,%2};" : "=l"(o) : "f"(lo), "f"(hi)); return o;
}
__device__ __forceinline__ float2 unpack2(u64 a) {
    float2 r; asm("mov.b64 {%0,%1},%2;" : "=f"(r.x), "=f"(r.y) : "l"(a)); return r;
}

// scratch (allocation-free rule: __device__ globals)
__device__ float d_g1[2 * 1024 * 64];
__device__ float d_g2[2 * 1024 * 8];
__device__ float d_c2[2 * 1024];
__device__ unsigned d_bits[2 * 1024 * 32];

// ---------------------------------------------------------------------------
// gemm1: out[M,64] = X[M,128] @ W1[64,128]^T.
// Full W staged transposed once (33KB, 1 barrier). Each thread computes TWO
// rows (r0, r0+4) at one column: 2x FMA per LDS, 8 accumulator chains, and
// every LDG.128 of x is a warp-broadcast (lanes share the row address).
// Block = 256 thr = 4 row-groups x 64 cols; 8 rows/block, grid 256.
// ---------------------------------------------------------------------------
__global__ __launch_bounds__(256) void gemm1_kernel(
    const float* __restrict__ X, const float* __restrict__ W,
    float* __restrict__ out) {
    constexpr int D = 128, K = 64;
    __shared__ float wsh[D * (K + 1)];
    int tid = threadIdx.x;
    for (int idx = tid; idx < D * K; idx += 256) {
        int c = idx / D, d = idx % D;
        wsh[d * (K + 1) + c] = W[idx];
    }
    __syncthreads();
    int c = tid & 63, rq = tid >> 6;          // rq in [0,4)
    int r0 = blockIdx.x * 8 + rq;             // rows r0 and r0+4
    const float4* xa4 = (const float4*)(X + (size_t)r0 * D);
    const float4* xb4 = (const float4*)(X + (size_t)(r0 + 4) * D);
    float a0 = 0.f, a1 = 0.f, a2 = 0.f, a3 = 0.f;
    float b0 = 0.f, b1 = 0.f, b2 = 0.f, b3 = 0.f;
#pragma unroll
    for (int d4 = 0; d4 < D / 4; d4++) {
        float4 xa = __ldg(xa4 + d4);
        float4 xb = __ldg(xb4 + d4);
        float w0 = wsh[(d4 * 4 + 0) * (K + 1) + c];
        float w1 = wsh[(d4 * 4 + 1) * (K + 1) + c];
        float w2 = wsh[(d4 * 4 + 2) * (K + 1) + c];
        float w3 = wsh[(d4 * 4 + 3) * (K + 1) + c];
        a0 = fmaf(xa.x, w0, a0); b0 = fmaf(xb.x, w0, b0);
        a1 = fmaf(xa.y, w1, a1); b1 = fmaf(xb.y, w1, b1);
        a2 = fmaf(xa.z, w2, a2); b2 = fmaf(xb.z, w2, b2);
        a3 = fmaf(xa.w, w3, a3); b3 = fmaf(xb.w, w3, b3);
    }
    out[(size_t)r0 * K + c] = (a0 + a1) + (a2 + a3);
    out[(size_t)(r0 + 4) * K + c] = (b0 + b1) + (b2 + b3);
}

// ---------------------------------------------------------------------------
// attn layer 1: H=8, F=8. CTA = 512 thr = 16 warps = 4 rows x 4 j-splits.
// TJ=128 tiles; adjacency INTS staged to smem each tile (R3-measured form),
// ballot-packed to the global bitmask as a byproduct (for attn2).
// Inline score: e = sum_f (0.6*log2e*a_f)*(s + (2/3)|s|), s = g_i + g_j.
// lane = jg*8 + h. g tile stride 12/head (conflict-free LDS.128); staging
// q-permuted (conflict-free STS.128); adj LDS.32 is 4-addr broadcast.
// Epilogue: ELU then fused row-local gemm2 (g2[r] = W2 @ h1[r]) + C2.
// ---------------------------------------------------------------------------
__global__ __launch_bounds__(512, 2) void attn1_kernel(
    const float* __restrict__ G, const int* __restrict__ ADJ,
    const float* __restrict__ AW,
    const float* __restrict__ W2, const float* __restrict__ A2,
    float* __restrict__ G2, float* __restrict__ C2,
    unsigned* __restrict__ BITSOUT, int N) {
    constexpr int S = 96;
    constexpr int TJ = 128;

    extern __shared__ float smem[];
    float* gsh = smem;                      // TJ*S        = 12288
    float* psum = gsh + TJ * S;             // 16*8*9      = 1152
    float* w2sh = psum + 16 * 8 * 9;        // 8*64        = 512
    int* ash = (int*)(w2sh + 512);          // 4*TJ        = 512 ints

    int tid = threadIdx.x;
    int w = tid >> 5, lane = tid & 31;
    int r = w & 3, sp = w >> 2;
    int h = lane & 7, jg = lane >> 3;
    int base = sp * 4 + jg;            // [0,16)

    int iflat = blockIdx.x * 4 + r;
    int b = iflat >> 10;
    int i0 = (blockIdx.x * 4) & 1023;

    if (tid < 512) w2sh[tid] = W2[tid];

    const float* gp = G + (size_t)iflat * 64 + h * 8;
    float4 gi0 = *(const float4*)gp;
    float4 gi1 = *(const float4*)(gp + 4);
    u64 gp01 = pack2(gi0.x, gi0.y), gp23 = pack2(gi0.z, gi0.w);
    u64 gp45 = pack2(gi1.x, gi1.y), gp67 = pack2(gi1.z, gi1.w);

    u64 aw[4];
#pragma unroll
    for (int k = 0; k < 4; k++)
        aw[k] = pack2(0.6f * LOG2E * __ldg(AW + 2 * k),
                      0.6f * LOG2E * __ldg(AW + 2 * k + 1));
    const u64 c23 = pack2(2.f / 3.f, 2.f / 3.f);
    const u64 amask = 0x7fffffff7fffffffULL;

    float l = 0.f;
    u64 a01 = 0, a23 = 0, a45 = 0, a67 = 0;

    const float4* gbase = (const float4*)(G + (size_t)b * N * 64);
    const int* abase = ADJ + (size_t)b * N * N + (size_t)i0 * N;
    const float* gl = gsh + base * S + h * 12;

    // this thread's adjacency staging slot: row srr, column sj of the tile
    int srr = tid >> 7, sj = tid & 127;
    unsigned* bitsrow = BITSOUT + (size_t)(blockIdx.x * 4 + srr) * 32;
    int sword = (tid >> 5) & 3;        // word within tile for this warp

    for (int jt = 0; jt < N; jt += TJ) {
        __syncthreads();
        const float4* src = gbase + (size_t)jt * 16;
        for (int idx = tid; idx < TJ * 16; idx += 512) {
            int j = idx >> 4, qidx = idx & 15;
            int q = ((qidx & 7) << 1) | (qidx >> 3);
            *(float4*)&gsh[j * S + (q >> 1) * 12 + (q & 1) * 4] = src[(j << 4) | q];
        }
        {   // adjacency ints: one per thread; ballot-pack bits as byproduct
            int v = __ldg(abase + (size_t)srr * N + jt + sj);
            ash[tid] = v;
            unsigned mword = __ballot_sync(0xffffffffu, v != 0);
            if (lane == 0) bitsrow[(jt >> 5) + sword] = mword;
        }
        __syncthreads();

#pragma unroll
        for (int k = 0; k < 8; k++) {
            const float* gr = gl + k * (16 * S);
            ulonglong2 v0 = *(const ulonglong2*)gr;
            ulonglong2 v1 = *(const ulonglong2*)(gr + 4);
            int m = ash[r * TJ + base + 16 * k];

            u64 s01 = add2(gp01, v0.x), s23 = add2(gp23, v0.y);
            u64 s45 = add2(gp45, v1.x), s67 = add2(gp67, v1.y);
            u64 d = mul2(aw[0], fma2(s01 & amask, c23, s01));
            d = fma2(aw[1], fma2(s23 & amask, c23, s23), d);
            d = fma2(aw[2], fma2(s45 & amask, c23, s45), d);
            d = fma2(aw[3], fma2(s67 & amask, c23, s67), d);
            float2 ev = unpack2(d);
            float wgt = m ? fexp2(ev.x + ev.y) : 0.f;
            l += wgt;
            u64 wp = pack2(wgt, wgt);
            a01 = fma2(wp, v0.x, a01);
            a23 = fma2(wp, v0.y, a23);
            a45 = fma2(wp, v1.x, a45);
            a67 = fma2(wp, v1.y, a67);
        }
    }

    // intra-warp reduce across jg strips (plain sums — max-free softmax)
    float2 f01 = unpack2(a01), f23 = unpack2(a23), f45 = unpack2(a45), f67 = unpack2(a67);
    float acc[8] = {f01.x, f01.y, f23.x, f23.y, f45.x, f45.y, f67.x, f67.y};
#pragma unroll
    for (int off = 8; off < 32; off <<= 1) {
        l += __shfl_xor_sync(0xffffffffu, l, off);
#pragma unroll
        for (int f = 0; f < 8; f++) acc[f] += __shfl_xor_sync(0xffffffffu, acc[f], off);
    }

    if (jg == 0) {
        float* p = psum + (w * 8 + h) * 9;
        p[0] = l;
#pragma unroll
        for (int f = 0; f < 8; f++) p[1 + f] = acc[f];
    }
    __syncthreads();
    if (sp == 0 && jg == 0) {   // warps 0..3 (w == r), lanes 0..7 (lane == h)
        float L = 0.f, A[8] = {0, 0, 0, 0, 0, 0, 0, 0};
#pragma unroll
        for (int ss = 0; ss < 4; ss++) {
            const float* p = psum + ((ss * 4 + r) * 8 + h) * 9;
            L += p[0];
#pragma unroll
            for (int f = 0; f < 8; f++) A[f] += p[1 + f];
        }
        float inv = 1.f / L;
        float o[8];
#pragma unroll
        for (int f = 0; f < 8; f++) {
            o[f] = A[f] * inv;
            o[f] = o[f] > 0.f ? o[f] : fexp2(o[f] * LOG2E) - 1.f;  // ELU
        }
        // fused gemm2: pk[k] = sum_f W2[k, h*8+f] * o[f]; reduce over 8 h-lanes
        float pk[8];
#pragma unroll
        for (int k = 0; k < 8; k++) {
            const float* wrow = w2sh + k * 64 + h * 8;
            float s = wrow[0] * o[0];
            s = fmaf(wrow[1], o[1], s);
            s = fmaf(wrow[2], o[2], s);
            s = fmaf(wrow[3], o[3], s);
            s = fmaf(wrow[4], o[4], s);
            s = fmaf(wrow[5], o[5], s);
            s = fmaf(wrow[6], o[6], s);
            s = fmaf(wrow[7], o[7], s);
            pk[k] = s;
        }
#pragma unroll
        for (int off = 1; off < 8; off <<= 1) {
#pragma unroll
            for (int k = 0; k < 8; k++)
                pk[k] += __shfl_xor_sync(0x000000ffu, pk[k], off);
        }
        if (h == 0) {
            float* op = G2 + (size_t)iflat * 8;
            *(float4*)op = make_float4(pk[0], pk[1], pk[2], pk[3]);
            *(float4*)(op + 4) = make_float4(pk[4], pk[5], pk[6], pk[7]);
            float cacc = 0.f;
#pragma unroll
            for (int k = 0; k < 8; k++) cacc = fmaf(pk[k], __ldg(A2 + k), cacc);
            C2[iflat] = 0.6f * LOG2E * cacc;
        }
    }
}

// ---------------------------------------------------------------------------
// attn layer 2: H=1, F=8 (best-measured R10 form). CTA = 256 thr = 8 warps =
// 8 rows, grid 256. Whole g2 batch staged once; C2 separate stride-1.
// Lane L owns j = L + 32k; 32 fully-unrolled iterations; full-warp reduce.
// Score uses the softmax-invariant C2 trick: e = C2[j] + 0.4*log2e*sum a|s|.
// ---------------------------------------------------------------------------
__global__ __launch_bounds__(256) void attn2_kernel(
    const float* __restrict__ G, const unsigned* __restrict__ BITS,
    const float* __restrict__ C, const float* __restrict__ AW,
    float* __restrict__ OUT, int N) {
    extern __shared__ float smem[];
    float* gsh = smem;            // N*12
    float* csh = smem + N * 12;   // N

    int tid = threadIdx.x;
    int w = tid >> 5, lane = tid & 31;
    int iflat = blockIdx.x * 8 + w;
    int b = iflat >> 10;

    const float4* gb = (const float4*)(G + (size_t)b * N * 8);
    const float* cb = C + (size_t)b * N;
    {
        int jb = tid & 127, q = tid >> 7;  // phase: same q, consecutive j
#pragma unroll
        for (int it = 0; it < 8; it++) {
            int j = jb + it * 128;
            *(float4*)&gsh[j * 12 + q * 4] = gb[j * 2 + q];
        }
    }
    for (int idx = tid; idx < N; idx += 256) csh[idx] = cb[idx];
    __syncthreads();

    const float* gp = G + (size_t)iflat * 8;
    float4 gi0 = *(const float4*)gp;
    float4 gi1 = *(const float4*)(gp + 4);
    u64 gp01 = pack2(gi0.x, gi0.y), gp23 = pack2(gi0.z, gi0.w);
    u64 gp45 = pack2(gi1.x, gi1.y), gp67 = pack2(gi1.z, gi1.w);

    u64 aw[4];
#pragma unroll
    for (int k = 0; k < 4; k++)
        aw[k] = pack2(0.4f * LOG2E * __ldg(AW + 2 * k),
                      0.4f * LOG2E * __ldg(AW + 2 * k + 1));
    const u64 amask = 0x7fffffff7fffffffULL;

    const uint4* b4 = (const uint4*)(BITS + (size_t)iflat * 32);
    const float* gl = gsh + lane * 12;
    const float* cl = csh + lane;

    float l = 0.f;
    u64 a01 = 0, a23 = 0, a45 = 0, a67 = 0;

#pragma unroll
    for (int kk = 0; kk < 8; kk++) {
        uint4 bw = b4[kk];
#pragma unroll
        for (int k2 = 0; k2 < 4; k2++) {
            const float* gr = gl + (kk * 4 + k2) * (32 * 12);
            ulonglong2 v0 = *(const ulonglong2*)gr;
            ulonglong2 v1 = *(const ulonglong2*)(gr + 4);
            float cj = cl[(kk * 4 + k2) * 32];
            unsigned wv = (k2 == 0) ? bw.x : (k2 == 1) ? bw.y : (k2 == 2) ? bw.z : bw.w;
            unsigned m = (wv >> lane) & 1u;

            u64 s01 = add2(gp01, v0.x), s23 = add2(gp23, v0.y);
            u64 s45 = add2(gp45, v1.x), s67 = add2(gp67, v1.y);
            u64 d = mul2(aw[0], s01 & amask);
            d = fma2(aw[1], s23 & amask, d);
            d = fma2(aw[2], s45 & amask, d);
            d = fma2(aw[3], s67 & amask, d);
            float2 ev = unpack2(d);
            float e = (ev.x + ev.y) + cj;
            float wgt = m ? fexp2(e) : 0.f;
            l += wgt;
            u64 wp = pack2(wgt, wgt);
            a01 = fma2(wp, v0.x, a01);
            a23 = fma2(wp, v0.y, a23);
            a45 = fma2(wp, v1.x, a45);
            a67 = fma2(wp, v1.y, a67);
        }
    }

    float2 f01 = unpack2(a01), f23 = unpack2(a23), f45 = unpack2(a45), f67 = unpack2(a67);
    float acc[8] = {f01.x, f01.y, f23.x, f23.y, f45.x, f45.y, f67.x, f67.y};
#pragma unroll
    for (int off = 1; off < 32; off <<= 1) {
        l += __shfl_xor_sync(0xffffffffu, l, off);
#pragma unroll
        for (int f = 0; f < 8; f++) acc[f] += __shfl_xor_sync(0xffffffffu, acc[f], off);
    }

    if (lane == 0) {
        float inv = 1.f / l;
        float* op = OUT + (size_t)iflat * 8;
        *(float4*)op = make_float4(acc[0] * inv, acc[1] * inv, acc[2] * inv, acc[3] * inv);
        *(float4*)(op + 4) = make_float4(acc[4] * inv, acc[5] * inv, acc[6] * inv, acc[7] * inv);
    }
}

// ---------------------------------------------------------------------------

extern "C" void kernel_launch(void* const* d_in, const int* in_sizes, int n_in,
                              void* d_out, int out_size) {
    const float* x = (const float*)d_in[0];
    const int* adj = (const int*)d_in[1];
    const float* W1 = (const float*)d_in[2];
    const float* a1 = (const float*)d_in[3];
    const float* W2 = (const float*)d_in[4];
    const float* a2 = (const float*)d_in[5];
    float* out = (float*)d_out;

    const int B = 2, N = 1024, M = B * N;

    float *g1, *g2, *c2;
    unsigned* bits;
    cudaGetSymbolAddress((void**)&g1, d_g1);
    cudaGetSymbolAddress((void**)&g2, d_g2);
    cudaGetSymbolAddress((void**)&c2, d_c2);
    cudaGetSymbolAddress((void**)&bits, d_bits);

    const int SMEM1 = (128 * 96 + 16 * 8 * 9 + 512 + 512) * 4;  // 57856
    const int SMEM2 = (N * 12 + N) * 4;                          // 53248
    cudaFuncSetAttribute((const void*)attn1_kernel,
                         cudaFuncAttributeMaxDynamicSharedMemorySize, SMEM1);
    cudaFuncSetAttribute((const void*)attn2_kernel,
                         cudaFuncAttributeMaxDynamicSharedMemorySize, SMEM2);

    // K1: gemm1 (2 rows/thread, 8 rows/block)
    gemm1_kernel<<<M / 8, 256>>>(x, W1, g1);
    // K2: attn1 (+ELU +gemm2 +C2 +bitmask production fused)
    attn1_kernel<<<M / 4, 512, SMEM1>>>(g1, adj, a1, W2, a2, g2, c2, bits, N);
    // K3: attn2
    attn2_kernel<<<M / 8, 256, SMEM2>>>(g2, bits, c2, a2, out, N);
}

// round 17
// speedup vs baseline: 1.1200x; 1.0245x over previous
#include <cuda_runtime.h>
#include <cstdint>

// GATv2 2-layer forward.
// x[2,1024,128], adj[2,1024,1024] i32, W1[64,128], a1[8], W2[8,64], a2[8]
// out[2,1024,8] f32
//
// 3 launches: gemm1 -> attn1(+ELU+gemm2+C2+bits fused) -> attn2.
// gemm1 stages BOTH X-rows and W into smem cooperatively (all DRAM latency
// absorbed by one massively-parallel staging phase), compute is smem-only.
// attn1 stages adjacency ints per tile (R3-measured fastest form, inline
// leaky score) and ballot-packs the bitmask attn2 consumes (free byproduct).
// attn2 uses the softmax-invariant C2 trick: e' = C2[j] + 0.4*log2e*sum a|s|.
// Max-free softmax throughout (scores O(1); partials sum linearly).
// h1 never touches global memory (row-local gemm2 in attn1's epilogue).

#define LOG2E 1.4426950408889634f
typedef unsigned long long u64;
typedef unsigned int u32;

__device__ __forceinline__ float fexp2(float x) {
    float y;
    asm("ex2.approx.ftz.f32 %0, %1;" : "=f"(y) : "f"(x));
    return y;
}
__device__ __forceinline__ u64 add2(u64 a, u64 b) {
    u64 o; asm("add.rn.f32x2 %0,%1,%2;" : "=l"(o) : "l"(a), "l"(b)); return o;
}
__device__ __forceinline__ u64 mul2(u64 a, u64 b) {
    u64 o; asm("mul.rn.f32x2 %0,%1,%2;" : "=l"(o) : "l"(a), "l"(b)); return o;
}
__device__ __forceinline__ u64 fma2(u64 a, u64 b, u64 c) {
    u64 o; asm("fma.rn.f32x2 %0,%1,%2,%3;" : "=l"(o) : "l"(a), "l"(b), "l"(c)); return o;
}
__device__ __forceinline__ u64 pack2(float lo, float hi) {
    u64 o; asm("mov.b64 %0,{%1,%2};" : "=l"(o) : "f"(lo), "f"(hi)); return o;
}
__device__ __forceinline__ float2 unpack2(u64 a) {
    float2 r; asm("mov.b64 {%0,%1},%2;" : "=f"(r.x), "=f"(r.y) : "l"(a)); return r;
}

// scratch (allocation-free rule: __device__ globals)
__device__ float d_g1[2 * 1024 * 64];
__device__ float d_g2[2 * 1024 * 8];
__device__ float d_c2[2 * 1024];
__device__ unsigned d_bits[2 * 1024 * 32];

// ---------------------------------------------------------------------------
// gemm1: out[M,64] = X[M,128] @ W1[64,128]^T.
// Stage X rows (4KB) + W transposed (33KB) cooperatively -> ALL global loads
// are independent and issued by 256 threads at once (DRAM latency hidden).
// Compute phase is pure smem: x via broadcast LDS.128, w via conflict-free
// stride-65 LDS.32; each thread does rows (rq, rq+4) at one column.
// Block = 256 thr, 8 rows/block, grid 256.
// ---------------------------------------------------------------------------
__global__ __launch_bounds__(256) void gemm1_kernel(
    const float* __restrict__ X, const float* __restrict__ W,
    float* __restrict__ out) {
    constexpr int D = 128, K = 64;
    __shared__ float wsh[D * (K + 1)];
    __shared__ float xsh[8 * D];
    int tid = threadIdx.x;
    // stage X: one float4 per thread (8 rows * 32 float4)
    {
        const float4* x4 = (const float4*)X + (size_t)blockIdx.x * 256;
        *(float4*)&xsh[tid * 4] = __ldg(x4 + tid);
    }
    // stage W transposed (scalar coalesced loads)
    for (int idx = tid; idx < D * K; idx += 256) {
        int c = idx / D, d = idx % D;
        wsh[d * (K + 1) + c] = W[idx];
    }
    __syncthreads();
    int c = tid & 63, rq = tid >> 6;          // rq in [0,4)
    int r0 = blockIdx.x * 8 + rq;             // rows rq and rq+4 of the tile
    const float* xa = xsh + rq * D;
    const float* xb = xsh + (rq + 4) * D;
    float a0 = 0.f, a1 = 0.f, a2 = 0.f, a3 = 0.f;
    float b0 = 0.f, b1 = 0.f, b2 = 0.f, b3 = 0.f;
#pragma unroll
    for (int d4 = 0; d4 < D / 4; d4++) {
        float4 xav = *(const float4*)(xa + d4 * 4);
        float4 xbv = *(const float4*)(xb + d4 * 4);
        float w0 = wsh[(d4 * 4 + 0) * (K + 1) + c];
        float w1 = wsh[(d4 * 4 + 1) * (K + 1) + c];
        float w2 = wsh[(d4 * 4 + 2) * (K + 1) + c];
        float w3 = wsh[(d4 * 4 + 3) * (K + 1) + c];
        a0 = fmaf(xav.x, w0, a0); b0 = fmaf(xbv.x, w0, b0);
        a1 = fmaf(xav.y, w1, a1); b1 = fmaf(xbv.y, w1, b1);
        a2 = fmaf(xav.z, w2, a2); b2 = fmaf(xbv.z, w2, b2);
        a3 = fmaf(xav.w, w3, a3); b3 = fmaf(xbv.w, w3, b3);
    }
    out[(size_t)r0 * K + c] = (a0 + a1) + (a2 + a3);
    out[(size_t)(r0 + 4) * K + c] = (b0 + b1) + (b2 + b3);
}

// ---------------------------------------------------------------------------
// attn layer 1: H=8, F=8. CTA = 512 thr = 16 warps = 4 rows x 4 j-splits.
// TJ=128 tiles; adjacency INTS staged to smem each tile (R3-measured form),
// ballot-packed to the global bitmask as a byproduct (for attn2).
// Inline score: e = sum_f (0.6*log2e*a_f)*(s + (2/3)|s|), s = g_i + g_j.
// lane = jg*8 + h. g tile stride 12/head (conflict-free LDS.128); staging
// q-permuted (conflict-free STS.128); adj LDS.32 is 4-addr broadcast.
// Epilogue: ELU then fused row-local gemm2 (g2[r] = W2 @ h1[r]) + C2.
// ---------------------------------------------------------------------------
__global__ __launch_bounds__(512, 2) void attn1_kernel(
    const float* __restrict__ G, const int* __restrict__ ADJ,
    const float* __restrict__ AW,
    const float* __restrict__ W2, const float* __restrict__ A2,
    float* __restrict__ G2, float* __restrict__ C2,
    unsigned* __restrict__ BITSOUT, int N) {
    constexpr int S = 96;
    constexpr int TJ = 128;

    extern __shared__ float smem[];
    float* gsh = smem;                      // TJ*S        = 12288
    float* psum = gsh + TJ * S;             // 16*8*9      = 1152
    float* w2sh = psum + 16 * 8 * 9;        // 8*64        = 512
    int* ash = (int*)(w2sh + 512);          // 4*TJ        = 512 ints

    int tid = threadIdx.x;
    int w = tid >> 5, lane = tid & 31;
    int r = w & 3, sp = w >> 2;
    int h = lane & 7, jg = lane >> 3;
    int base = sp * 4 + jg;            // [0,16)

    int iflat = blockIdx.x * 4 + r;
    int b = iflat >> 10;
    int i0 = (blockIdx.x * 4) & 1023;

    if (tid < 512) w2sh[tid] = W2[tid];

    const float* gp = G + (size_t)iflat * 64 + h * 8;
    float4 gi0 = *(const float4*)gp;
    float4 gi1 = *(const float4*)(gp + 4);
    u64 gp01 = pack2(gi0.x, gi0.y), gp23 = pack2(gi0.z, gi0.w);
    u64 gp45 = pack2(gi1.x, gi1.y), gp67 = pack2(gi1.z, gi1.w);

    u64 aw[4];
#pragma unroll
    for (int k = 0; k < 4; k++)
        aw[k] = pack2(0.6f * LOG2E * __ldg(AW + 2 * k),
                      0.6f * LOG2E * __ldg(AW + 2 * k + 1));
    const u64 c23 = pack2(2.f / 3.f, 2.f / 3.f);
    const u64 amask = 0x7fffffff7fffffffULL;

    float l = 0.f;
    u64 a01 = 0, a23 = 0, a45 = 0, a67 = 0;

    const float4* gbase = (const float4*)(G + (size_t)b * N * 64);
    const int* abase = ADJ + (size_t)b * N * N + (size_t)i0 * N;
    const float* gl = gsh + base * S + h * 12;

    // this thread's adjacency staging slot: row srr, column sj of the tile
    int srr = tid >> 7, sj = tid & 127;
    unsigned* bitsrow = BITSOUT + (size_t)(blockIdx.x * 4 + srr) * 32;
    int sword = (tid >> 5) & 3;        // word within tile for this warp

    for (int jt = 0; jt < N; jt += TJ) {
        __syncthreads();
        const float4* src = gbase + (size_t)jt * 16;
        for (int idx = tid; idx < TJ * 16; idx += 512) {
            int j = idx >> 4, qidx = idx & 15;
            int q = ((qidx & 7) << 1) | (qidx >> 3);
            *(float4*)&gsh[j * S + (q >> 1) * 12 + (q & 1) * 4] = src[(j << 4) | q];
        }
        {   // adjacency ints: one per thread; ballot-pack bits as byproduct
            int v = __ldg(abase + (size_t)srr * N + jt + sj);
            ash[tid] = v;
            unsigned mword = __ballot_sync(0xffffffffu, v != 0);
            if (lane == 0) bitsrow[(jt >> 5) + sword] = mword;
        }
        __syncthreads();

#pragma unroll
        for (int k = 0; k < 8; k++) {
            const float* gr = gl + k * (16 * S);
            ulonglong2 v0 = *(const ulonglong2*)gr;
            ulonglong2 v1 = *(const ulonglong2*)(gr + 4);
            int m = ash[r * TJ + base + 16 * k];

            u64 s01 = add2(gp01, v0.x), s23 = add2(gp23, v0.y);
            u64 s45 = add2(gp45, v1.x), s67 = add2(gp67, v1.y);
            u64 d = mul2(aw[0], fma2(s01 & amask, c23, s01));
            d = fma2(aw[1], fma2(s23 & amask, c23, s23), d);
            d = fma2(aw[2], fma2(s45 & amask, c23, s45), d);
            d = fma2(aw[3], fma2(s67 & amask, c23, s67), d);
            float2 ev = unpack2(d);
            float wgt = m ? fexp2(ev.x + ev.y) : 0.f;
            l += wgt;
            u64 wp = pack2(wgt, wgt);
            a01 = fma2(wp, v0.x, a01);
            a23 = fma2(wp, v0.y, a23);
            a45 = fma2(wp, v1.x, a45);
            a67 = fma2(wp, v1.y, a67);
        }
    }

    // intra-warp reduce across jg strips (plain sums — max-free softmax)
    float2 f01 = unpack2(a01), f23 = unpack2(a23), f45 = unpack2(a45), f67 = unpack2(a67);
    float acc[8] = {f01.x, f01.y, f23.x, f23.y, f45.x, f45.y, f67.x, f67.y};
#pragma unroll
    for (int off = 8; off < 32; off <<= 1) {
        l += __shfl_xor_sync(0xffffffffu, l, off);
#pragma unroll
        for (int f = 0; f < 8; f++) acc[f] += __shfl_xor_sync(0xffffffffu, acc[f], off);
    }

    if (jg == 0) {
        float* p = psum + (w * 8 + h) * 9;
        p[0] = l;
#pragma unroll
        for (int f = 0; f < 8; f++) p[1 + f] = acc[f];
    }
    __syncthreads();
    if (sp == 0 && jg == 0) {   // warps 0..3 (w == r), lanes 0..7 (lane == h)
        float L = 0.f, A[8] = {0, 0, 0, 0, 0, 0, 0, 0};
#pragma unroll
        for (int ss = 0; ss < 4; ss++) {
            const float* p = psum + ((ss * 4 + r) * 8 + h) * 9;
            L += p[0];
#pragma unroll
            for (int f = 0; f < 8; f++) A[f] += p[1 + f];
        }
        float inv = 1.f / L;
        float o[8];
#pragma unroll
        for (int f = 0; f < 8; f++) {
            o[f] = A[f] * inv;
            o[f] = o[f] > 0.f ? o[f] : fexp2(o[f] * LOG2E) - 1.f;  // ELU
        }
        // fused gemm2: pk[k] = sum_f W2[k, h*8+f] * o[f]; reduce over 8 h-lanes
        float pk[8];
#pragma unroll
        for (int k = 0; k < 8; k++) {
            const float* wrow = w2sh + k * 64 + h * 8;
            float s = wrow[0] * o[0];
            s = fmaf(wrow[1], o[1], s);
            s = fmaf(wrow[2], o[2], s);
            s = fmaf(wrow[3], o[3], s);
            s = fmaf(wrow[4], o[4], s);
            s = fmaf(wrow[5], o[5], s);
            s = fmaf(wrow[6], o[6], s);
            s = fmaf(wrow[7], o[7], s);
            pk[k] = s;
        }
#pragma unroll
        for (int off = 1; off < 8; off <<= 1) {
#pragma unroll
            for (int k = 0; k < 8; k++)
                pk[k] += __shfl_xor_sync(0x000000ffu, pk[k], off);
        }
        if (h == 0) {
            float* op = G2 + (size_t)iflat * 8;
            *(float4*)op = make_float4(pk[0], pk[1], pk[2], pk[3]);
            *(float4*)(op + 4) = make_float4(pk[4], pk[5], pk[6], pk[7]);
            float cacc = 0.f;
#pragma unroll
            for (int k = 0; k < 8; k++) cacc = fmaf(pk[k], __ldg(A2 + k), cacc);
            C2[iflat] = 0.6f * LOG2E * cacc;
        }
    }
}

// ---------------------------------------------------------------------------
// attn layer 2: H=1, F=8 (best-measured R10 form). CTA = 256 thr = 8 warps =
// 8 rows, grid 256. Whole g2 batch staged once; C2 separate stride-1.
// Lane L owns j = L + 32k; 32 fully-unrolled iterations; full-warp reduce.
// ---------------------------------------------------------------------------
__global__ __launch_bounds__(256) void attn2_kernel(
    const float* __restrict__ G, const unsigned* __restrict__ BITS,
    const float* __restrict__ C, const float* __restrict__ AW,
    float* __restrict__ OUT, int N) {
    extern __shared__ float smem[];
    float* gsh = smem;            // N*12
    float* csh = smem + N * 12;   // N

    int tid = threadIdx.x;
    int w = tid >> 5, lane = tid & 31;
    int iflat = blockIdx.x * 8 + w;
    int b = iflat >> 10;

    const float4* gb = (const float4*)(G + (size_t)b * N * 8);
    const float* cb = C + (size_t)b * N;
    {
        int jb = tid & 127, q = tid >> 7;  // phase: same q, consecutive j
#pragma unroll
        for (int it = 0; it < 8; it++) {
            int j = jb + it * 128;
            *(float4*)&gsh[j * 12 + q * 4] = gb[j * 2 + q];
        }
    }
    for (int idx = tid; idx < N; idx += 256) csh[idx] = cb[idx];
    __syncthreads();

    const float* gp = G + (size_t)iflat * 8;
    float4 gi0 = *(const float4*)gp;
    float4 gi1 = *(const float4*)(gp + 4);
    u64 gp01 = pack2(gi0.x, gi0.y), gp23 = pack2(gi0.z, gi0.w);
    u64 gp45 = pack2(gi1.x, gi1.y), gp67 = pack2(gi1.z, gi1.w);

    u64 aw[4];
#pragma unroll
    for (int k = 0; k < 4; k++)
        aw[k] = pack2(0.4f * LOG2E * __ldg(AW + 2 * k),
                      0.4f * LOG2E * __ldg(AW + 2 * k + 1));
    const u64 amask = 0x7fffffff7fffffffULL;

    const uint4* b4 = (const uint4*)(BITS + (size_t)iflat * 32);
    const float* gl = gsh + lane * 12;
    const float* cl = csh + lane;

    float l = 0.f;
    u64 a01 = 0, a23 = 0, a45 = 0, a67 = 0;

#pragma unroll
    for (int kk = 0; kk < 8; kk++) {
        uint4 bw = b4[kk];
#pragma unroll
        for (int k2 = 0; k2 < 4; k2++) {
            const float* gr = gl + (kk * 4 + k2) * (32 * 12);
            ulonglong2 v0 = *(const ulonglong2*)gr;
            ulonglong2 v1 = *(const ulonglong2*)(gr + 4);
            float cj = cl[(kk * 4 + k2) * 32];
            unsigned wv = (k2 == 0) ? bw.x : (k2 == 1) ? bw.y : (k2 == 2) ? bw.z : bw.w;
            unsigned m = (wv >> lane) & 1u;

            u64 s01 = add2(gp01, v0.x), s23 = add2(gp23, v0.y);
            u64 s45 = add2(gp45, v1.x), s67 = add2(gp67, v1.y);
            u64 d = mul2(aw[0], s01 & amask);
            d = fma2(aw[1], s23 & amask, d);
            d = fma2(aw[2], s45 & amask, d);
            d = fma2(aw[3], s67 & amask, d);
            float2 ev = unpack2(d);
            float e = (ev.x + ev.y) + cj;
            float wgt = m ? fexp2(e) : 0.f;
            l += wgt;
            u64 wp = pack2(wgt, wgt);
            a01 = fma2(wp, v0.x, a01);
            a23 = fma2(wp, v0.y, a23);
            a45 = fma2(wp, v1.x, a45);
            a67 = fma2(wp, v1.y, a67);
        }
    }

    float2 f01 = unpack2(a01), f23 = unpack2(a23), f45 = unpack2(a45), f67 = unpack2(a67);
    float acc[8] = {f01.x, f01.y, f23.x, f23.y, f45.x, f45.y, f67.x, f67.y};
#pragma unroll
    for (int off = 1; off < 32; off <<= 1) {
        l += __shfl_xor_sync(0xffffffffu, l, off);
#pragma unroll
        for (int f = 0; f < 8; f++) acc[f] += __shfl_xor_sync(0xffffffffu, acc[f], off);
    }

    if (lane == 0) {
        float inv = 1.f / l;
        float* op = OUT + (size_t)iflat * 8;
        *(float4*)op = make_float4(acc[0] * inv, acc[1] * inv, acc[2] * inv, acc[3] * inv);
        *(float4*)(op + 4) = make_float4(acc[4] * inv, acc[5] * inv, acc[6] * inv, acc[7] * inv);
    }
}

// ---------------------------------------------------------------------------

extern "C" void kernel_launch(void* const* d_in, const int* in_sizes, int n_in,
                              void* d_out, int out_size) {
    const float* x = (const float*)d_in[0];
    const int* adj = (const int*)d_in[1];
    const float* W1 = (const float*)d_in[2];
    const float* a1 = (const float*)d_in[3];
    const float* W2 = (const float*)d_in[4];
    const float* a2 = (const float*)d_in[5];
    float* out = (float*)d_out;

    const int B = 2, N = 1024, M = B * N;

    float *g1, *g2, *c2;
    unsigned* bits;
    cudaGetSymbolAddress((void**)&g1, d_g1);
    cudaGetSymbolAddress((void**)&g2, d_g2);
    cudaGetSymbolAddress((void**)&c2, d_c2);
    cudaGetSymbolAddress((void**)&bits, d_bits);

    const int SMEM1 = (128 * 96 + 16 * 8 * 9 + 512 + 512) * 4;  // 57856
    const int SMEM2 = (N * 12 + N) * 4;                          // 53248
    cudaFuncSetAttribute((const void*)attn1_kernel,
                         cudaFuncAttributeMaxDynamicSharedMemorySize, SMEM1);
    cudaFuncSetAttribute((const void*)attn2_kernel,
                         cudaFuncAttributeMaxDynamicSharedMemorySize, SMEM2);

    // K1: gemm1 (X+W staged cooperatively; smem-only compute)
    gemm1_kernel<<<M / 8, 256>>>(x, W1, g1);
    // K2: attn1 (+ELU +gemm2 +C2 +bitmask production fused)
    attn1_kernel<<<M / 4, 512, SMEM1>>>(g1, adj, a1, W2, a2, g2, c2, bits, N);
    // K3: attn2
    attn2_kernel<<<M / 8, 256, SMEM2>>>(g2, bits, c2, a2, out, N);
}